// round 7
// baseline (speedup 1.0000x reference)
#include <cuda_runtime.h>
#include <math.h>

#define Bq 32
#define Tn 256
#define Hn 512
#define G4 2048
#define RR 4
#define CELLn 64
#define NCn 64
#define XIn 471
#define EPSf 1e-6f
#define CLIPf 50000.0f
#define NBLK 128
#define NTHR 256

// ---------------- persistent device scratch (no allocation) ----------------
__device__ float d_h[Bq*Hn];
__device__ float d_c[Bq*Hn];
__device__ float d_M[Bq*NCn*CELLn];
__device__ float d_u[Bq*NCn];
__device__ float d_p[Bq*NCn];
__device__ float d_L[Bq*NCn*NCn];
__device__ float d_wr[Bq*RR*NCn];
__device__ float d_ww[Bq*NCn];
__device__ float d_r[Bq*RR*CELLn];
__device__ float d_gp[6][Bq*G4];          // gate partials (6 k-slices)
__device__ float d_Hbuf[Bq*Tn*Hn];        // all h_t for deferred Y GEMM
__device__ float d_Rbuf[Bq*Tn*RR*CELLn];  // all r_t
__device__ float d_Wxip[512*512];         // W_xi padded 471 -> 512 cols
__device__ unsigned g_barcnt;
__device__ unsigned g_hflag;
__device__ unsigned g_rflag;

__device__ __forceinline__ float sigmoidf_(float x){ return 1.f/(1.f+expf(-x)); }
__device__ __forceinline__ float softplusf_(float x){ return (x > 20.f) ? x : log1pf(expf(x)); }

// ---------------- software grid barrier (128 co-resident blocks) ----------------
__device__ __forceinline__ void grid_bar(unsigned &epoch){
    epoch++;
    __threadfence();
    __syncthreads();
    if (threadIdx.x == 0){
        atomicAdd(&g_barcnt, 1u);
        while (*(volatile unsigned*)&g_barcnt < epoch * NBLK) { }
    }
    __syncthreads();
    __threadfence();
}

// ---------------- init ----------------
__global__ void k_init(){
    int tid = blockIdx.x*blockDim.x + threadIdx.x;
    int stride = gridDim.x*blockDim.x;
    if (tid == 0){ g_barcnt = 0u; g_hflag = 0u; g_rflag = 0u; }
    for (int i=tid;i<Bq*Hn;i+=stride){ d_h[i]=0.f; d_c[i]=0.f; }
    for (int i=tid;i<Bq*NCn*CELLn;i+=stride){ d_M[i]=0.f; d_L[i]=0.f; }
    for (int i=tid;i<Bq*NCn;i+=stride){ d_u[i]=0.f; d_p[i]=0.f; d_ww[i]=0.f; }
    for (int i=tid;i<Bq*RR*NCn;i+=stride){ d_wr[i]=0.f; d_r[i]=0.f; }
}

// ---------------- prep: pad W_xi (512x471) into (512x512) ----------------
__global__ void k_prep(const float* __restrict__ W_xi){
    int idx = blockIdx.x*blockDim.x + threadIdx.x;
    if (idx < 512*512){
        int k = idx >> 9;
        int j = idx & 511;
        d_Wxip[idx] = (j < XIn) ? W_xi[k*XIn + j] : 0.f;
    }
}

// dummies so k_mega lands on ncu's captured launch slot
__global__ void k_dummy(){}

// ---------------- shared memory union ----------------
struct SA { int sIdx[32]; float As[224][36]; float Ws[32][128]; };
struct SD {
    float Ms[NCn*65]; float Ls[NCn*65]; float xiS[512]; float hs[512];
    float us[64], ps[64], wws[64], wrs[256];
    float eraseS[64], wvecS[64];
    float freeS[4], betar[4], krn[4], piS[12];
    float mnorm[64], cww[64], su[64], pe[64], aS[64];
    int   rankof[64];
    float fwd[256], bwd[256], cwr[256];
    float scal[8], mx4[4], sm4[4];
};
union __align__(16) SMEM { SA a; SD d; };

// ---------------- DNC memory update for one batch (xiS prefilled in S) ----------------
__device__ void dnc_step(SD& S, int b, int tid, int td){
    const int lane = tid & 31;

    // D0: state load (xiS already computed in-block)
#pragma unroll
    for (int q=0; q<16; q++){
        int idx = tid + q*NTHR;
        int n = idx >> 6, w = idx & 63;
        S.Ms[n*65+w] = d_M[b*NCn*CELLn + idx];
        S.Ls[n*65+w] = d_L[b*NCn*NCn + idx];
    }
    if (tid < NCn){
        S.us[tid]=d_u[b*NCn+tid]; S.ps[tid]=d_p[b*NCn+tid]; S.wws[tid]=d_ww[b*NCn+tid];
    }
    S.wrs[tid] = d_wr[b*RR*NCn + tid];
    __syncthreads();

    // D1: extract xi fields
    if (tid < CELLn){ S.eraseS[tid] = sigmoidf_(S.xiS[325+tid]); S.wvecS[tid] = S.xiS[389+tid]; }
    else if (tid >= 64 && tid < 64+RR){
        int i = tid-64;
        S.freeS[i] = sigmoidf_(S.xiS[453+i]);
        S.betar[i] = 1.f + softplusf_(S.xiS[256+i]);
        float s0=0.f, s1=0.f;
#pragma unroll
        for (int w=0;w<CELLn;w+=2){
            float v0 = S.xiS[i*CELLn+w], v1 = S.xiS[i*CELLn+w+1];
            s0 += v0*v0; s1 += v1*v1;
        }
        S.krn[i] = sqrtf(s0+s1) + EPSf;
    }
    else if (tid >= 96 && tid < 96+RR){
        int i = tid-96;
        float p0=S.xiS[459+i*3], p1=S.xiS[460+i*3], p2=S.xiS[461+i*3];
        float m = fmaxf(p0, fmaxf(p1,p2));
        float e0=expf(p0-m), e1=expf(p1-m), e2=expf(p2-m);
        float s = e0+e1+e2;
        S.piS[i*3+0]=e0/s; S.piS[i*3+1]=e1/s; S.piS[i*3+2]=e2/s;
    }
    else if (tid == 128){
        float s0=0.f, s1=0.f;
#pragma unroll
        for (int w=0;w<CELLn;w+=2){
            float v0=S.xiS[260+w], v1=S.xiS[260+w+1];
            s0+=v0*v0; s1+=v1*v1;
        }
        S.scal[0] = sqrtf(s0+s1) + EPSf;
    }
    else if (tid == 129) S.scal[1] = 1.f + softplusf_(S.xiS[324]);
    else if (tid == 130) S.scal[2] = sigmoidf_(S.xiS[457]);
    else if (tid == 131) S.scal[3] = sigmoidf_(S.xiS[458]);
    __syncthreads();

    // D2: write content sim + usage update (4 threads/cell)
    {
        int n = tid >> 2, s4 = tid & 3;
        float rn=0.f, dt=0.f;
#pragma unroll
        for (int w8=0; w8<16; w8++){
            int w = s4*16 + w8;
            float mv = S.Ms[n*65+w];
            rn += mv*mv;
            dt += mv*S.xiS[260+w];
        }
        rn += __shfl_down_sync(0xffffffffu, rn, 2);
        rn += __shfl_down_sync(0xffffffffu, rn, 1);
        dt += __shfl_down_sync(0xffffffffu, dt, 2);
        dt += __shfl_down_sync(0xffffffffu, dt, 1);
        if (s4 == 0){
            float mn = sqrtf(rn) + EPSf;
            S.cww[n] = dt/(mn*S.scal[0]) * S.scal[1];
            float psi = 1.f;
#pragma unroll
            for (int i=0;i<RR;i++) psi *= (1.f - S.freeS[i]*S.wrs[i*NCn+n]);
            float u = S.us[n], w0 = S.wws[n];
            S.us[n] = (u + w0 - u*w0) * psi;
        }
    }
    __syncthreads();

    // D3: cww max (warp0) + stable rank (tid 64..127)
    if (tid < 32){
        float m = fmaxf(S.cww[tid], S.cww[tid+32]);
#pragma unroll
        for (int o=16;o>0;o>>=1) m = fmaxf(m, __shfl_xor_sync(0xffffffffu, m, o));
        if (lane == 0) S.scal[5] = m;
    } else if (tid >= 64 && tid < 128){
        int n = tid-64; float un = S.us[n]; int rk=0;
#pragma unroll
        for (int j=0;j<NCn;j++){
            float uj = S.us[j];
            rk += (uj < un) || (uj == un && j < n);
        }
        S.su[rk] = un; S.rankof[n] = rk;
    }
    __syncthreads();

    // D4: exp + exclusive cumprod (shuffle scan)
    if (tid < NCn) S.cww[tid] = expf(S.cww[tid]-S.scal[5]);
    else if (tid >= 64 && tid < 96){
        int l = tid-64;
        float a = S.su[2*l], bb = S.su[2*l+1];
        float Sx = a*bb;
#pragma unroll
        for (int o=1;o<32;o<<=1){
            float u2 = __shfl_up_sync(0xffffffffu, Sx, o);
            if (l >= o) Sx *= u2;
        }
        float X = __shfl_up_sync(0xffffffffu, Sx, 1);
        if (l == 0) X = 1.f;
        S.pe[2*l]   = X;
        S.pe[2*l+1] = X*a;
    }
    __syncthreads();

    // D5: cww sum + allocation
    if (tid < 32){
        float s = S.cww[tid] + S.cww[tid+32];
#pragma unroll
        for (int o=16;o>0;o>>=1) s += __shfl_xor_sync(0xffffffffu, s, o);
        if (lane == 0) S.scal[6] = s;
    } else if (tid >= 64 && tid < 128){
        int n = tid-64;
        int rk = S.rankof[n];
        S.aS[n] = (1.f - S.su[rk]) * S.pe[rk];
    }
    __syncthreads();

    // D6: write weighting
    if (tid < NCn){
        float c = S.cww[tid]/S.scal[6];
        S.wws[tid] = S.scal[3]*(S.scal[2]*S.aS[tid] + (1.f-S.scal[2])*c);
    }
    __syncthreads();

    // D6b: wsum
    if (tid < 32){
        float s = S.wws[tid] + S.wws[tid+32];
#pragma unroll
        for (int o=16;o>0;o>>=1) s += __shfl_xor_sync(0xffffffffu, s, o);
        if (lane == 0) S.scal[4] = s;
    }
    __syncthreads();

    // D7: M and L update
#pragma unroll
    for (int q=0; q<16; q++){
        int idx = tid + q*NTHR;
        int n = idx >> 6, w = idx & 63;
        float wwn = S.wws[n];
        S.Ms[n*65+w] = S.Ms[n*65+w]*(1.f - wwn*S.eraseS[w]) + wwn*S.wvecS[w];
        float lv = (n==w) ? 0.f : ((1.f - wwn - S.wws[w])*S.Ls[n*65+w] + wwn*S.ps[w]);
        S.Ls[n*65+w] = lv;
    }
    __syncthreads();

    // D8: fwd/bwd
    {
        int i = tid >> 6, n = tid & 63;
        float f0=0.f, f1=0.f, bw0=0.f, bw1=0.f;
#pragma unroll
        for (int m=0;m<NCn;m+=2){
            float wv0 = S.wrs[i*NCn+m];
            float wv1 = S.wrs[i*NCn+m+1];
            f0  += S.Ls[n*65+m]*wv0;
            f1  += S.Ls[n*65+m+1]*wv1;
            bw0 += S.Ls[m*65+n]*wv0;
            bw1 += S.Ls[(m+1)*65+n]*wv1;
        }
        S.fwd[tid]=f0+f1; S.bwd[tid]=bw0+bw1;
    }
    __syncthreads();

    // D9: p update + new M norms
    if (tid < NCn) S.ps[tid] = (1.f - S.scal[4])*S.ps[tid] + S.wws[tid];
    __syncthreads();
    {
        int n = tid >> 2, s4 = tid & 3;
        float s=0.f;
#pragma unroll
        for (int w8=0; w8<16; w8++){
            int w = s4*16 + w8;
            float v = S.Ms[n*65+w];
            s += v*v;
        }
        s += __shfl_down_sync(0xffffffffu, s, 2);
        s += __shfl_down_sync(0xffffffffu, s, 1);
        if (s4 == 0) S.mnorm[n] = sqrtf(s) + EPSf;
    }
    __syncthreads();

    // D10: read content sims
    {
        int i = tid >> 6, n = tid & 63;
        float d0=0.f, d1=0.f;
#pragma unroll
        for (int w=0;w<CELLn;w+=2){
            d0 += S.Ms[n*65+w]*S.xiS[i*CELLn+w];
            d1 += S.Ms[n*65+w+1]*S.xiS[i*CELLn+w+1];
        }
        S.cwr[tid] = (d0+d1)/(S.mnorm[n]*S.krn[i]) * S.betar[i];
    }
    __syncthreads();

    // D11: per-head max
    if (tid < 128){
        int r = tid >> 5;
        float m = fmaxf(S.cwr[r*64+lane], S.cwr[r*64+lane+32]);
#pragma unroll
        for (int o=16;o>0;o>>=1) m = fmaxf(m, __shfl_xor_sync(0xffffffffu, m, o));
        if (lane == 0) S.mx4[r] = m;
    }
    __syncthreads();

    // D12: exp
    S.cwr[tid] = expf(S.cwr[tid]-S.mx4[tid>>6]);
    __syncthreads();

    // D13: per-head sum
    if (tid < 128){
        int r = tid >> 5;
        float s = S.cwr[r*64+lane] + S.cwr[r*64+lane+32];
#pragma unroll
        for (int o=16;o>0;o>>=1) s += __shfl_xor_sync(0xffffffffu, s, o);
        if (lane == 0) S.sm4[r] = s;
    }
    __syncthreads();

    // D14: new read weights
    {
        int i = tid >> 6;
        S.wrs[tid] = S.piS[i*3+0]*S.bwd[tid]
                   + S.piS[i*3+1]*(S.cwr[tid]/S.sm4[i])
                   + S.piS[i*3+2]*S.fwd[tid];
    }
    __syncthreads();

    // D15: reads + writeback
    {
        int i = tid >> 6, w = tid & 63;
        float r0=0.f, r1=0.f;
#pragma unroll
        for (int n=0;n<NCn;n+=2){
            r0 += S.wrs[i*NCn+n]*S.Ms[n*65+w];
            r1 += S.wrs[i*NCn+n+1]*S.Ms[(n+1)*65+w];
        }
        float rv = r0+r1;
        d_r[b*RR*CELLn + tid] = rv;
        d_Rbuf[((size_t)b*Tn+td)*RR*CELLn + tid] = rv;
    }
#pragma unroll
    for (int q=0; q<16; q++){
        int idx = tid + q*NTHR;
        int n = idx >> 6, w = idx & 63;
        d_M[b*NCn*CELLn + idx] = S.Ms[n*65+w];
        d_L[b*NCn*NCn  + idx] = S.Ls[n*65+w];
    }
    if (tid < NCn){
        d_u[b*NCn+tid]=S.us[tid]; d_p[b*NCn+tid]=S.ps[tid]; d_ww[b*NCn+tid]=S.wws[tid];
    }
    d_wr[b*RR*NCn + tid] = S.wrs[tid];
}

// W row pointer for global k in [0,1280): x->Wih[0:512), h->Whh, r->Wih[512:768)
__device__ __forceinline__ const float* w_row(int k, const float* Wih, const float* Whh){
    if (k < 512)  return Wih + (size_t)k*G4;
    if (k < 1024) return Whh + (size_t)(k-512)*G4;
    return Wih + (size_t)(512 + k-1024)*G4;
}

// ---------------- the persistent mega kernel ----------------
__global__ void __launch_bounds__(NTHR, 1)
k_mega(const int* __restrict__ src,
       const float* __restrict__ emb,
       const float* __restrict__ Wih,
       const float* __restrict__ Whh,
       const float* __restrict__ b_lstm,
       const float* __restrict__ b_xi){
    __shared__ SMEM sm;
    const int bid = blockIdx.x;
    const int tid = threadIdx.x;
    unsigned epoch = 0;

    // gate-slice geometry (bid>=32): 16 j-tiles x 6 k-slices
    const int s  = (bid-32) >> 4;     // 0..5
    const int jb = (bid-32) & 15;
    const int j0 = jb*128;
    const int nxh = (s < 4) ? 6 : 4;                         // x/h chunks
    const int xhb = (s < 4) ? s*192 : 768 + (s-4)*128;       // k-base of x/h range
    const int nr  = (s < 4) ? 1 : 2;                         // r chunks
    const int rb  = (s < 4) ? s*32 : 128 + (s-4)*64;         // offset within r
    const int nx  = (xhb < 512) ? min(nxh, (512 - xhb) >> 5) : 0;  // pure-x chunks
    const int nct = nxh + nr;

    for (int t=0; t<=Tn; t++){
        if (bid < 32){
            // ===== D path: h-reduce(t-1) -> hflag -> xi GEMM -> dnc(t-1) -> rflag =====
            if (t > 0){
                const int b = bid;
#pragma unroll
                for (int q=0; q<2; q++){
                    int i = tid + q*NTHR;
                    float gi = b_lstm[i], gf = b_lstm[512+i], gg = b_lstm[1024+i], go = b_lstm[1536+i];
#pragma unroll
                    for (int ks=0; ks<6; ks++){
                        const float* gb = d_gp[ks] + (size_t)b*G4;
                        gi += gb[i]; gf += gb[512+i]; gg += gb[1024+i]; go += gb[1536+i];
                    }
                    float c = sigmoidf_(gf)*d_c[b*Hn+i] + sigmoidf_(gi)*tanhf(gg);
                    float h = sigmoidf_(go)*tanhf(c);
                    d_c[b*Hn+i]=c; d_h[b*Hn+i]=h;
                    d_Hbuf[((size_t)b*Tn+(t-1))*Hn + i] = h;
                    sm.d.hs[i] = h;
                }
                __threadfence();
                __syncthreads();
                if (tid == 0) atomicAdd(&g_hflag, 1u);

                // xi = h @ W_xi (+ bias), in-block
                {
                    const int jq = (tid & 127) << 2;
                    const int kh = tid >> 7;
                    float a0=0.f,a1=0.f,a2=0.f,a3=0.f;
                    const float* wp = d_Wxip + (size_t)(kh*256)*512 + jq;
                    const float* hp = sm.d.hs + kh*256;
#pragma unroll 8
                    for (int k=0;k<256;k++){
                        float hv = hp[k];
                        float4 w = *(const float4*)wp; wp += 512;
                        a0 += hv*w.x; a1 += hv*w.y; a2 += hv*w.z; a3 += hv*w.w;
                    }
                    if (kh == 0){
                        sm.d.xiS[jq+0] = a0 + ((jq+0 < XIn) ? b_xi[jq+0] : 0.f);
                        sm.d.xiS[jq+1] = a1 + ((jq+1 < XIn) ? b_xi[jq+1] : 0.f);
                        sm.d.xiS[jq+2] = a2 + ((jq+2 < XIn) ? b_xi[jq+2] : 0.f);
                        sm.d.xiS[jq+3] = a3 + ((jq+3 < XIn) ? b_xi[jq+3] : 0.f);
                    }
                    __syncthreads();
                    if (kh == 1){
                        sm.d.xiS[jq+0] += a0; sm.d.xiS[jq+1] += a1;
                        sm.d.xiS[jq+2] += a2; sm.d.xiS[jq+3] += a3;
                    }
                    __syncthreads();
                }

                dnc_step(sm.d, b, tid, t-1);
                __threadfence();
                __syncthreads();
                if (tid == 0) atomicAdd(&g_rflag, 1u);
            }
        } else if (t < Tn){
            // ===== gate path: chunks x -> (wait h) h -> (wait r) r =====
            const int tx = tid & 31;
            const int ty = tid >> 5;

            if (tid < 32) sm.a.sIdx[tid] = src[tid*Tn + t];
            __syncthreads();

            // stage X: preload pure-x rows
            for (int q = tid; q < nx*256; q += NTHR){
                int b  = q & 31;
                int kq = (q >> 5) << 2;
                float4 av = *(const float4*)(emb + (size_t)sm.a.sIdx[b]*Hn + xhb + kq);
                sm.a.As[kq+0][b]=av.x; sm.a.As[kq+1][b]=av.y;
                sm.a.As[kq+2][b]=av.z; sm.a.As[kq+3][b]=av.w;
            }

            float acc[4][4];
#pragma unroll
            for (int i=0;i<4;i++)
#pragma unroll
                for (int j=0;j<4;j++) acc[i][j]=0.f;

            // prefetch W chunk 0
            float4 wreg[4];
            {
                int k0 = (0 < nxh) ? xhb : (1024 + rb);
#pragma unroll
                for (int i=0;i<4;i++){
                    int idx = tid + i*256;
                    int kk = idx >> 5, j4 = (idx & 31) << 2;
                    wreg[i] = *(const float4*)(w_row(k0 + kk, Wih, Whh) + j0 + j4);
                }
            }

            for (int cc = 0; cc < nct; cc++){
                if (cc == nx && nxh > nx){
                    // need h(t-1): wait flag, then load h rows
                    if (tid == 0){
                        unsigned target = 32u*(unsigned)t;
                        while (*(volatile unsigned*)&g_hflag < target) { }
                    }
                    __syncthreads();
                    __threadfence();
                    for (int q = tid; q < (nxh-nx)*256; q += NTHR){
                        int b  = q & 31;
                        int kq = (q >> 5) << 2;
                        int row = nx*32 + kq;
                        float4 av = *(const float4*)(d_h + b*Hn + (xhb + row - 512));
                        sm.a.As[row+0][b]=av.x; sm.a.As[row+1][b]=av.y;
                        sm.a.As[row+2][b]=av.z; sm.a.As[row+3][b]=av.w;
                    }
                }
                if (cc == nxh){
                    // need r(t-1): wait flag, then load r rows
                    if (tid == 0){
                        unsigned target = 32u*(unsigned)t;
                        while (*(volatile unsigned*)&g_rflag < target) { }
                    }
                    __syncthreads();
                    __threadfence();
                    for (int q = tid; q < nr*256; q += NTHR){
                        int b  = q & 31;
                        int kq = (q >> 5) << 2;
                        int row = nxh*32 + kq;
                        float4 av = *(const float4*)(d_r + b*(RR*CELLn) + rb + kq);
                        sm.a.As[row+0][b]=av.x; sm.a.As[row+1][b]=av.y;
                        sm.a.As[row+2][b]=av.z; sm.a.As[row+3][b]=av.w;
                    }
                }
                __syncthreads();
#pragma unroll
                for (int i=0;i<4;i++){
                    int idx = tid + i*256;
                    int kk = idx >> 5, j4 = (idx & 31) << 2;
                    *(float4*)&sm.a.Ws[kk][j4] = wreg[i];
                }
                __syncthreads();
                if (cc < nct-1){
                    int kgb = (cc+1 < nxh) ? (xhb + (cc+1)*32) : (1024 + rb + (cc+1-nxh)*32);
#pragma unroll
                    for (int i=0;i<4;i++){
                        int idx = tid + i*256;
                        int kk = idx >> 5, j4 = (idx & 31) << 2;
                        wreg[i] = *(const float4*)(w_row(kgb + kk, Wih, Whh) + j0 + j4);
                    }
                }
                const int kb = cc*32;
#pragma unroll
                for (int kk=0; kk<32; kk++){
                    float4 a = *(const float4*)&sm.a.As[kb+kk][ty<<2];
                    float4 w = *(const float4*)&sm.a.Ws[kk][tx<<2];
                    acc[0][0]+=a.x*w.x; acc[0][1]+=a.x*w.y; acc[0][2]+=a.x*w.z; acc[0][3]+=a.x*w.w;
                    acc[1][0]+=a.y*w.x; acc[1][1]+=a.y*w.y; acc[1][2]+=a.y*w.z; acc[1][3]+=a.y*w.w;
                    acc[2][0]+=a.z*w.x; acc[2][1]+=a.z*w.y; acc[2][2]+=a.z*w.z; acc[2][3]+=a.z*w.w;
                    acc[3][0]+=a.w*w.x; acc[3][1]+=a.w*w.y; acc[3][2]+=a.w*w.z; acc[3][3]+=a.w*w.w;
                }
            }
            // store this slice's partial
            float* gp = d_gp[s];
#pragma unroll
            for (int c=0;c<4;c++){
                int b = (ty<<2)+c;
                *(float4*)(gp + (size_t)b*G4 + j0 + (tx<<2)) =
                    make_float4(acc[c][0],acc[c][1],acc[c][2],acc[c][3]);
            }
        }
        if (t < Tn) grid_bar(epoch);
    }
}

// ---------------- K3: deferred output GEMM Y = [H|R] @ W_out + b, clip ----------------
__global__ void __launch_bounds__(256) k_y(const float* __restrict__ Wout,
                                           const float* __restrict__ bout,
                                           float* __restrict__ out){
    __shared__ float As[64][17];
    __shared__ float Ws[16][64];
    const int row0 = blockIdx.x*64;
    const int col0 = blockIdx.y*64;
    const int tid = threadIdx.x;
    const int tx = tid & 15;
    const int ty = tid >> 4;

    float acc[4][4];
#pragma unroll
    for (int i=0;i<4;i++)
#pragma unroll
        for (int j=0;j<4;j++) acc[i][j]=0.f;

    for (int k0=0;k0<768;k0+=16){
        {
            int r = tid >> 2;
            int kq = (tid & 3) << 2;
            int k = k0 + kq;
            float4 av;
            if (k < 512) av = *(const float4*)(d_Hbuf + (size_t)(row0+r)*Hn + k);
            else         av = *(const float4*)(d_Rbuf + (size_t)(row0+r)*(RR*CELLn) + (k-512));
            As[r][kq+0]=av.x; As[r][kq+1]=av.y; As[r][kq+2]=av.z; As[r][kq+3]=av.w;
        }
        {
            int kk = tid >> 4;
            int c4 = (tid & 15) << 2;
            *(float4*)&Ws[kk][c4] = *(const float4*)(Wout + (size_t)(k0+kk)*Hn + col0 + c4);
        }
        __syncthreads();
#pragma unroll
        for (int kk=0;kk<16;kk++){
            float4 w = *(const float4*)&Ws[kk][tx<<2];
            float a0 = As[(ty<<2)+0][kk];
            float a1 = As[(ty<<2)+1][kk];
            float a2 = As[(ty<<2)+2][kk];
            float a3 = As[(ty<<2)+3][kk];
            acc[0][0]+=a0*w.x; acc[0][1]+=a0*w.y; acc[0][2]+=a0*w.z; acc[0][3]+=a0*w.w;
            acc[1][0]+=a1*w.x; acc[1][1]+=a1*w.y; acc[1][2]+=a1*w.z; acc[1][3]+=a1*w.w;
            acc[2][0]+=a2*w.x; acc[2][1]+=a2*w.y; acc[2][2]+=a2*w.z; acc[2][3]+=a2*w.w;
            acc[3][0]+=a3*w.x; acc[3][1]+=a3*w.y; acc[3][2]+=a3*w.z; acc[3][3]+=a3*w.w;
        }
        __syncthreads();
    }
    float4 bb = *(const float4*)(bout + col0 + (tx<<2));
#pragma unroll
    for (int i=0;i<4;i++){
        int row = row0 + (ty<<2) + i;
        float4 v;
        v.x = fminf(fmaxf(acc[i][0]+bb.x,-CLIPf),CLIPf);
        v.y = fminf(fmaxf(acc[i][1]+bb.y,-CLIPf),CLIPf);
        v.z = fminf(fmaxf(acc[i][2]+bb.z,-CLIPf),CLIPf);
        v.w = fminf(fmaxf(acc[i][3]+bb.w,-CLIPf),CLIPf);
        *(float4*)(out + (size_t)row*Hn + col0 + (tx<<2)) = v;
    }
}

// ---------------- launch ----------------
extern "C" void kernel_launch(void* const* d_in, const int* in_sizes, int n_in,
                              void* d_out, int out_size){
    (void)in_sizes; (void)n_in; (void)out_size;
    const int*   source = (const int*)  d_in[0];
    const float* emb    = (const float*)d_in[2];
    const float* Wih    = (const float*)d_in[3];
    const float* Whh    = (const float*)d_in[4];
    const float* b_lstm = (const float*)d_in[5];
    const float* W_xi   = (const float*)d_in[6];
    const float* b_xi   = (const float*)d_in[7];
    const float* W_out  = (const float*)d_in[8];
    const float* b_out  = (const float*)d_in[9];
    float* out = (float*)d_out;

    k_init<<<128,256>>>();
    k_prep<<<1024,256>>>(W_xi);
    k_dummy<<<1,1>>>();
    k_dummy<<<1,1>>>();     // with harness's hidden launch, k_mega is captured slot
    k_mega<<<NBLK,NTHR>>>(source, emb, Wih, Whh, b_lstm, b_xi);
    k_y<<<dim3(128,8),256>>>(W_out, b_out, out);
}

// round 8
// speedup vs baseline: 1.0227x; 1.0227x over previous
#include <cuda_runtime.h>
#include <math.h>

#define Bq 32
#define Tn 256
#define Hn 512
#define G4 2048
#define RR 4
#define CELLn 64
#define NCn 64
#define XIn 471
#define EPSf 1e-6f
#define CLIPf 50000.0f
#define NBLK 128
#define NTHR 256

// ---------------- persistent device scratch (no allocation) ----------------
__device__ float d_h[Bq*Hn];
__device__ float d_cB[2][Bq*Hn];          // double-buffered LSTM cell state
__device__ float d_M[Bq*NCn*CELLn];
__device__ float d_u[Bq*NCn];
__device__ float d_p[Bq*NCn];
__device__ float d_L[Bq*NCn*NCn];
__device__ float d_wr[Bq*RR*NCn];
__device__ float d_ww[Bq*NCn];
__device__ float d_r[Bq*RR*CELLn];
__device__ float d_gp[6][Bq*G4];          // gate partials (6 k-slices, plain stores)
__device__ float d_xip[8][Bq*512];        // xi partials (8 k-slices, plain stores)
__device__ float d_Hbuf[Bq*Tn*Hn];        // all h_t for deferred Y GEMM
__device__ float d_Rbuf[Bq*Tn*RR*CELLn];  // all r_t
__device__ float d_Wxip[512*512];         // W_xi padded 471 -> 512 cols
__device__ unsigned g_barcnt;
__device__ unsigned g_rflag;

__device__ __forceinline__ float sigmoidf_(float x){ return 1.f/(1.f+expf(-x)); }
__device__ __forceinline__ float softplusf_(float x){ return (x > 20.f) ? x : log1pf(expf(x)); }

// ---------------- software grid barrier (128 co-resident blocks) ----------------
__device__ __forceinline__ void grid_bar(unsigned &epoch){
    epoch++;
    __threadfence();
    __syncthreads();
    if (threadIdx.x == 0){
        atomicAdd(&g_barcnt, 1u);
        while (*(volatile unsigned*)&g_barcnt < epoch * NBLK) { }
    }
    __syncthreads();
    __threadfence();
}

// ---------------- init ----------------
__global__ void k_init(){
    int tid = blockIdx.x*blockDim.x + threadIdx.x;
    int stride = gridDim.x*blockDim.x;
    if (tid == 0){ g_barcnt = 0u; g_rflag = 0u; }
    for (int i=tid;i<Bq*Hn;i+=stride){ d_h[i]=0.f; d_cB[0][i]=0.f; d_cB[1][i]=0.f; }
    for (int i=tid;i<Bq*NCn*CELLn;i+=stride){ d_M[i]=0.f; d_L[i]=0.f; }
    for (int i=tid;i<Bq*NCn;i+=stride){ d_u[i]=0.f; d_p[i]=0.f; d_ww[i]=0.f; }
    for (int i=tid;i<Bq*RR*NCn;i+=stride){ d_wr[i]=0.f; d_r[i]=0.f; }
}

// ---------------- prep: pad W_xi (512x471) into (512x512) ----------------
__global__ void k_prep(const float* __restrict__ W_xi){
    int idx = blockIdx.x*blockDim.x + threadIdx.x;
    if (idx < 512*512){
        int k = idx >> 9;
        int j = idx & 511;
        d_Wxip[idx] = (j < XIn) ? W_xi[k*XIn + j] : 0.f;
    }
}

// exactly ONE dummy: with the harness's 2 hidden launches, k_mega = process launch #6 (ncu -s 5 -c 1)
__global__ void k_dummy(){}

// ---------------- shared memory union ----------------
struct SA { int sIdx[32]; float As[224][36]; float Ws[32][128]; };
struct SC2 { float hs2[32][65]; float ws[64][32]; };
struct SD {
    float Ms[NCn*65]; float Ls[NCn*65]; float xiS[512];
    float us[64], ps[64], wws[64], wrs[256];
    float eraseS[64], wvecS[64];
    float freeS[4], betar[4], krn[4], piS[12];
    float mnorm[64], cww[64], su[64], pe[64], aS[64];
    int   rankof[64];
    float fwd[256], bwd[256], cwr[256];
    float scal[8], mx4[4], sm4[4];
};
union __align__(16) SMEM { SA a; SC2 c; SD d; };

// ---------------- DNC memory update for one batch (one block) ----------------
__device__ void dnc_step(SD& S, int b, int tid, int td, const float* __restrict__ b_xi){
    const int lane = tid & 31;

    // D0: xi = bias + 8 accumulated partials; state load
#pragma unroll
    for (int q=0; q<2; q++){
        int j = tid + q*NTHR;
        float v = (j < XIn) ? b_xi[j] : 0.f;
#pragma unroll
        for (int ks=0; ks<8; ks++) v += d_xip[ks][b*512 + j];
        S.xiS[j] = v;
    }
#pragma unroll
    for (int q=0; q<16; q++){
        int idx = tid + q*NTHR;
        int n = idx >> 6, w = idx & 63;
        S.Ms[n*65+w] = d_M[b*NCn*CELLn + idx];
        S.Ls[n*65+w] = d_L[b*NCn*NCn + idx];
    }
    if (tid < NCn){
        S.us[tid]=d_u[b*NCn+tid]; S.ps[tid]=d_p[b*NCn+tid]; S.wws[tid]=d_ww[b*NCn+tid];
    }
    S.wrs[tid] = d_wr[b*RR*NCn + tid];
    __syncthreads();

    // D1: extract xi fields
    if (tid < CELLn){ S.eraseS[tid] = sigmoidf_(S.xiS[325+tid]); S.wvecS[tid] = S.xiS[389+tid]; }
    else if (tid >= 64 && tid < 64+RR){
        int i = tid-64;
        S.freeS[i] = sigmoidf_(S.xiS[453+i]);
        S.betar[i] = 1.f + softplusf_(S.xiS[256+i]);
        float s0=0.f, s1=0.f;
#pragma unroll
        for (int w=0;w<CELLn;w+=2){
            float v0 = S.xiS[i*CELLn+w], v1 = S.xiS[i*CELLn+w+1];
            s0 += v0*v0; s1 += v1*v1;
        }
        S.krn[i] = sqrtf(s0+s1) + EPSf;
    }
    else if (tid >= 96 && tid < 96+RR){
        int i = tid-96;
        float p0=S.xiS[459+i*3], p1=S.xiS[460+i*3], p2=S.xiS[461+i*3];
        float m = fmaxf(p0, fmaxf(p1,p2));
        float e0=expf(p0-m), e1=expf(p1-m), e2=expf(p2-m);
        float s = e0+e1+e2;
        S.piS[i*3+0]=e0/s; S.piS[i*3+1]=e1/s; S.piS[i*3+2]=e2/s;
    }
    else if (tid == 128){
        float s0=0.f, s1=0.f;
#pragma unroll
        for (int w=0;w<CELLn;w+=2){
            float v0=S.xiS[260+w], v1=S.xiS[260+w+1];
            s0+=v0*v0; s1+=v1*v1;
        }
        S.scal[0] = sqrtf(s0+s1) + EPSf;
    }
    else if (tid == 129) S.scal[1] = 1.f + softplusf_(S.xiS[324]);
    else if (tid == 130) S.scal[2] = sigmoidf_(S.xiS[457]);
    else if (tid == 131) S.scal[3] = sigmoidf_(S.xiS[458]);
    __syncthreads();

    // D2: write content sim + usage update (4 threads/cell)
    {
        int n = tid >> 2, s4 = tid & 3;
        float rn=0.f, dt=0.f;
#pragma unroll
        for (int w8=0; w8<16; w8++){
            int w = s4*16 + w8;
            float mv = S.Ms[n*65+w];
            rn += mv*mv;
            dt += mv*S.xiS[260+w];
        }
        rn += __shfl_down_sync(0xffffffffu, rn, 2);
        rn += __shfl_down_sync(0xffffffffu, rn, 1);
        dt += __shfl_down_sync(0xffffffffu, dt, 2);
        dt += __shfl_down_sync(0xffffffffu, dt, 1);
        if (s4 == 0){
            float mn = sqrtf(rn) + EPSf;
            S.cww[n] = dt/(mn*S.scal[0]) * S.scal[1];
            float psi = 1.f;
#pragma unroll
            for (int i=0;i<RR;i++) psi *= (1.f - S.freeS[i]*S.wrs[i*NCn+n]);
            float u = S.us[n], w0 = S.wws[n];
            S.us[n] = (u + w0 - u*w0) * psi;
        }
    }
    __syncthreads();

    // D3: cww max (warp0) + stable rank (tid 64..127)
    if (tid < 32){
        float m = fmaxf(S.cww[tid], S.cww[tid+32]);
#pragma unroll
        for (int o=16;o>0;o>>=1) m = fmaxf(m, __shfl_xor_sync(0xffffffffu, m, o));
        if (lane == 0) S.scal[5] = m;
    } else if (tid >= 64 && tid < 128){
        int n = tid-64; float un = S.us[n]; int rk=0;
#pragma unroll
        for (int j=0;j<NCn;j++){
            float uj = S.us[j];
            rk += (uj < un) || (uj == un && j < n);
        }
        S.su[rk] = un; S.rankof[n] = rk;
    }
    __syncthreads();

    // D4: exp + exclusive cumprod (shuffle scan)
    if (tid < NCn) S.cww[tid] = expf(S.cww[tid]-S.scal[5]);
    else if (tid >= 64 && tid < 96){
        int l = tid-64;
        float a = S.su[2*l], bb = S.su[2*l+1];
        float Sx = a*bb;
#pragma unroll
        for (int o=1;o<32;o<<=1){
            float u2 = __shfl_up_sync(0xffffffffu, Sx, o);
            if (l >= o) Sx *= u2;
        }
        float X = __shfl_up_sync(0xffffffffu, Sx, 1);
        if (l == 0) X = 1.f;
        S.pe[2*l]   = X;
        S.pe[2*l+1] = X*a;
    }
    __syncthreads();

    // D5: cww sum + allocation
    if (tid < 32){
        float s = S.cww[tid] + S.cww[tid+32];
#pragma unroll
        for (int o=16;o>0;o>>=1) s += __shfl_xor_sync(0xffffffffu, s, o);
        if (lane == 0) S.scal[6] = s;
    } else if (tid >= 64 && tid < 128){
        int n = tid-64;
        int rk = S.rankof[n];
        S.aS[n] = (1.f - S.su[rk]) * S.pe[rk];
    }
    __syncthreads();

    // D6: write weighting
    if (tid < NCn){
        float c = S.cww[tid]/S.scal[6];
        S.wws[tid] = S.scal[3]*(S.scal[2]*S.aS[tid] + (1.f-S.scal[2])*c);
    }
    __syncthreads();

    // D6b: wsum
    if (tid < 32){
        float s = S.wws[tid] + S.wws[tid+32];
#pragma unroll
        for (int o=16;o>0;o>>=1) s += __shfl_xor_sync(0xffffffffu, s, o);
        if (lane == 0) S.scal[4] = s;
    }
    __syncthreads();

    // D7: M and L update
#pragma unroll
    for (int q=0; q<16; q++){
        int idx = tid + q*NTHR;
        int n = idx >> 6, w = idx & 63;
        float wwn = S.wws[n];
        S.Ms[n*65+w] = S.Ms[n*65+w]*(1.f - wwn*S.eraseS[w]) + wwn*S.wvecS[w];
        float lv = (n==w) ? 0.f : ((1.f - wwn - S.wws[w])*S.Ls[n*65+w] + wwn*S.ps[w]);
        S.Ls[n*65+w] = lv;
    }
    __syncthreads();

    // D8: fwd/bwd
    {
        int i = tid >> 6, n = tid & 63;
        float f0=0.f, f1=0.f, bw0=0.f, bw1=0.f;
#pragma unroll
        for (int m=0;m<NCn;m+=2){
            float wv0 = S.wrs[i*NCn+m];
            float wv1 = S.wrs[i*NCn+m+1];
            f0  += S.Ls[n*65+m]*wv0;
            f1  += S.Ls[n*65+m+1]*wv1;
            bw0 += S.Ls[m*65+n]*wv0;
            bw1 += S.Ls[(m+1)*65+n]*wv1;
        }
        S.fwd[tid]=f0+f1; S.bwd[tid]=bw0+bw1;
    }
    __syncthreads();

    // D9: p update + new M norms
    if (tid < NCn) S.ps[tid] = (1.f - S.scal[4])*S.ps[tid] + S.wws[tid];
    __syncthreads();
    {
        int n = tid >> 2, s4 = tid & 3;
        float s=0.f;
#pragma unroll
        for (int w8=0; w8<16; w8++){
            int w = s4*16 + w8;
            float v = S.Ms[n*65+w];
            s += v*v;
        }
        s += __shfl_down_sync(0xffffffffu, s, 2);
        s += __shfl_down_sync(0xffffffffu, s, 1);
        if (s4 == 0) S.mnorm[n] = sqrtf(s) + EPSf;
    }
    __syncthreads();

    // D10: read content sims
    {
        int i = tid >> 6, n = tid & 63;
        float d0=0.f, d1=0.f;
#pragma unroll
        for (int w=0;w<CELLn;w+=2){
            d0 += S.Ms[n*65+w]*S.xiS[i*CELLn+w];
            d1 += S.Ms[n*65+w+1]*S.xiS[i*CELLn+w+1];
        }
        S.cwr[tid] = (d0+d1)/(S.mnorm[n]*S.krn[i]) * S.betar[i];
    }
    __syncthreads();

    // D11: per-head max
    if (tid < 128){
        int r = tid >> 5;
        float m = fmaxf(S.cwr[r*64+lane], S.cwr[r*64+lane+32]);
#pragma unroll
        for (int o=16;o>0;o>>=1) m = fmaxf(m, __shfl_xor_sync(0xffffffffu, m, o));
        if (lane == 0) S.mx4[r] = m;
    }
    __syncthreads();

    // D12: exp
    S.cwr[tid] = expf(S.cwr[tid]-S.mx4[tid>>6]);
    __syncthreads();

    // D13: per-head sum
    if (tid < 128){
        int r = tid >> 5;
        float s = S.cwr[r*64+lane] + S.cwr[r*64+lane+32];
#pragma unroll
        for (int o=16;o>0;o>>=1) s += __shfl_xor_sync(0xffffffffu, s, o);
        if (lane == 0) S.sm4[r] = s;
    }
    __syncthreads();

    // D14: new read weights
    {
        int i = tid >> 6;
        S.wrs[tid] = S.piS[i*3+0]*S.bwd[tid]
                   + S.piS[i*3+1]*(S.cwr[tid]/S.sm4[i])
                   + S.piS[i*3+2]*S.fwd[tid];
    }
    __syncthreads();

    // D15: reads + writeback
    {
        int i = tid >> 6, w = tid & 63;
        float r0=0.f, r1=0.f;
#pragma unroll
        for (int n=0;n<NCn;n+=2){
            r0 += S.wrs[i*NCn+n]*S.Ms[n*65+w];
            r1 += S.wrs[i*NCn+n+1]*S.Ms[(n+1)*65+w];
        }
        float rv = r0+r1;
        d_r[b*RR*CELLn + tid] = rv;
        d_Rbuf[((size_t)b*Tn+td)*RR*CELLn + tid] = rv;
    }
#pragma unroll
    for (int q=0; q<16; q++){
        int idx = tid + q*NTHR;
        int n = idx >> 6, w = idx & 63;
        d_M[b*NCn*CELLn + idx] = S.Ms[n*65+w];
        d_L[b*NCn*NCn  + idx] = S.Ls[n*65+w];
    }
    if (tid < NCn){
        d_u[b*NCn+tid]=S.us[tid]; d_p[b*NCn+tid]=S.ps[tid]; d_ww[b*NCn+tid]=S.wws[tid];
    }
    d_wr[b*RR*NCn + tid] = S.wrs[tid];
}

// W row pointer for global k in [0,1280): x->Wih[0:512), h->Whh[0:512), r->Wih[512:768)
__device__ __forceinline__ const float* w_row(int k, const float* Wih, const float* Whh){
    if (k < 512)  return Wih + (size_t)k*G4;
    if (k < 1024) return Whh + (size_t)(k-512)*G4;
    return Wih + (size_t)(512 + k-1024)*G4;
}

// ---------------- the persistent mega kernel ----------------
__global__ void __launch_bounds__(NTHR, 1)
k_mega(const int* __restrict__ src,
       const float* __restrict__ emb,
       const float* __restrict__ Wih,
       const float* __restrict__ Whh,
       const float* __restrict__ b_lstm,
       const float* __restrict__ b_xi){
    __shared__ SMEM sm;
    const int bid = blockIdx.x;
    const int tid = threadIdx.x;
    unsigned epoch = 0;

    // A1 slice geometry (valid for bid>=32)
    const int jb  = (bid-32) & 15;
    const int ksl = (bid-32) >> 4;                 // 0..5
    const int ncx   = (ksl < 4) ? 6 : 4;           // x/h chunks
    const int ncr   = (ksl < 4) ? 1 : 2;           // r chunks
    const int nct   = ncx + ncr;
    const int xbase = (ksl < 4) ? ksl*192 : 768 + (ksl-4)*128;   // global k of x/h range
    const int rbase = (ksl < 4) ? ksl*32  : 128 + (ksl-4)*64;    // offset into r (k=1024+rbase)
    const int j0 = jb*128;

    for (int t=0; t<Tn; t++){
        // ======== P1: D(t-1) on blocks 0..31  ||  full gate GEMM on blocks 32..127 ========
        if (bid < 32){
            if (t > 0){
                dnc_step(sm.d, bid, tid, t-1, b_xi);
                __threadfence();
                __syncthreads();
                if (tid == 0) atomicAdd(&g_rflag, 1u);
            }
        } else {
            const int tx = tid & 31;
            const int ty = tid >> 5;

            if (tid < 32) sm.a.sIdx[tid] = src[tid*Tn + t];
            __syncthreads();

            // preload x/h portion of A panel
            for (int q = tid; q < ncx*256; q += NTHR){
                int b  = q & 31;
                int kq = (q >> 5) << 2;
                int kg = xbase + kq;
                float4 av = (kg < 512)
                    ? *(const float4*)(emb + (size_t)sm.a.sIdx[b]*Hn + kg)
                    : *(const float4*)(d_h + b*Hn + (kg-512));
                sm.a.As[kq+0][b]=av.x; sm.a.As[kq+1][b]=av.y;
                sm.a.As[kq+2][b]=av.z; sm.a.As[kq+3][b]=av.w;
            }

            float acc[4][4];
#pragma unroll
            for (int i=0;i<4;i++)
#pragma unroll
                for (int j=0;j<4;j++) acc[i][j]=0.f;

            // prefetch W chunk 0 into registers
            float4 wreg[4];
#pragma unroll
            for (int i=0;i<4;i++){
                int idx = tid + i*256;
                int kk = idx >> 5, j4 = (idx & 31) << 2;
                wreg[i] = *(const float4*)(w_row(xbase + kk, Wih, Whh) + j0 + j4);
            }

            for (int cc = 0; cc < nct; cc++){
                if (cc == ncx){
                    // r data needed from here on: wait for D(t-1), then load r panel
                    if (tid == 0){
                        unsigned target = 32u*(unsigned)t;
                        while (*(volatile unsigned*)&g_rflag < target) { }
                    }
                    __syncthreads();
                    __threadfence();   // acquire fresh d_r
                    for (int q = tid; q < ncr*256; q += NTHR){
                        int b  = q & 31;
                        int kq = (q >> 5) << 2;
                        float4 av = *(const float4*)(d_r + b*(RR*CELLn) + rbase + kq);
                        int pr = ncx*32 + kq;
                        sm.a.As[pr+0][b]=av.x; sm.a.As[pr+1][b]=av.y;
                        sm.a.As[pr+2][b]=av.z; sm.a.As[pr+3][b]=av.w;
                    }
                }
                __syncthreads();
#pragma unroll
                for (int i=0;i<4;i++){
                    int idx = tid + i*256;
                    int kk = idx >> 5, j4 = (idx & 31) << 2;
                    *(float4*)&sm.a.Ws[kk][j4] = wreg[i];
                }
                __syncthreads();
                if (cc < nct-1){
                    int kgb = (cc+1 < ncx) ? (xbase + (cc+1)*32) : (1024 + rbase + (cc+1-ncx)*32);
#pragma unroll
                    for (int i=0;i<4;i++){
                        int idx = tid + i*256;
                        int kk = idx >> 5, j4 = (idx & 31) << 2;
                        wreg[i] = *(const float4*)(w_row(kgb + kk, Wih, Whh) + j0 + j4);
                    }
                }
                const int kb = cc*32;
#pragma unroll
                for (int kk=0; kk<32; kk++){
                    float4 a = *(const float4*)&sm.a.As[kb+kk][ty<<2];
                    float4 w = *(const float4*)&sm.a.Ws[kk][tx<<2];
                    acc[0][0]+=a.x*w.x; acc[0][1]+=a.x*w.y; acc[0][2]+=a.x*w.z; acc[0][3]+=a.x*w.w;
                    acc[1][0]+=a.y*w.x; acc[1][1]+=a.y*w.y; acc[1][2]+=a.y*w.z; acc[1][3]+=a.y*w.w;
                    acc[2][0]+=a.z*w.x; acc[2][1]+=a.z*w.y; acc[2][2]+=a.z*w.z; acc[2][3]+=a.z*w.w;
                    acc[3][0]+=a.w*w.x; acc[3][1]+=a.w*w.y; acc[3][2]+=a.w*w.z; acc[3][3]+=a.w*w.w;
                }
            }
            // single plain store of the full k-slice partial
            float* gp = d_gp[ksl];
#pragma unroll
            for (int c=0;c<4;c++){
                int b = (ty<<2)+c;
                *(float4*)(gp + (size_t)b*G4 + j0 + (tx<<2)) =
                    make_float4(acc[c][0],acc[c][1],acc[c][2],acc[c][3]);
            }
        }
        grid_bar(epoch);

        // ======== P3: LSTM h (6-partial reduce); xi partials ========
        {
            const int jt = bid & 15;
            const int ksr = bid >> 4;

            const float* cOld = d_cB[t&1];
            float* cNew = d_cB[(t+1)&1];
#pragma unroll
            for (int q=0; q<8; q++){
                int idx = tid + q*NTHR;
                int b = idx >> 6, il = idx & 63;
                int i = ksr*64 + il;
                float gi = b_lstm[i], gf = b_lstm[512+i], gg = b_lstm[1024+i], go = b_lstm[1536+i];
#pragma unroll
                for (int ks=0; ks<6; ks++){
                    const float* gb = d_gp[ks] + (size_t)b*G4;
                    gi += gb[i]; gf += gb[512+i]; gg += gb[1024+i]; go += gb[1536+i];
                }
                float c = sigmoidf_(gf)*cOld[b*Hn+i] + sigmoidf_(gi)*tanhf(gg);
                float h = sigmoidf_(go)*tanhf(c);
                if (jt == 0){
                    cNew[b*Hn+i] = c;
                    d_h[b*Hn+i] = h;
                    d_Hbuf[((size_t)b*Tn+t)*Hn + i] = h;
                }
                sm.c.hs2[b][il] = h;
            }
            // W_xi tile [64k x 32j]
#pragma unroll
            for (int q=0; q<8; q++){
                int idx = tid + q*NTHR;
                int kk = idx >> 5, jj = idx & 31;
                sm.c.ws[kk][jj] = d_Wxip[(size_t)(ksr*64+kk)*512 + jt*32 + jj];
            }
            __syncthreads();
            // xi partial: 32 b x 32 j per block -> plain store to d_xip[ksr]
            {
                int b = tid >> 3;
                int j4 = (tid & 7) << 2;
                float a0=0.f,a1=0.f,a2=0.f,a3=0.f;
#pragma unroll 16
                for (int kk=0;kk<64;kk++){
                    float hv = sm.c.hs2[b][kk];
                    float4 w = *(const float4*)&sm.c.ws[kk][j4];
                    a0+=hv*w.x; a1+=hv*w.y; a2+=hv*w.z; a3+=hv*w.w;
                }
                *(float4*)&d_xip[ksr][(size_t)b*512 + jt*32 + j4] = make_float4(a0,a1,a2,a3);
            }
        }
        grid_bar(epoch);
    }

    // final D(Tn-1)
    if (bid < 32){
        dnc_step(sm.d, bid, tid, Tn-1, b_xi);
    }
}

// ---------------- K3: deferred output GEMM Y = [H|R] @ W_out + b, clip ----------------
__global__ void __launch_bounds__(256) k_y(const float* __restrict__ Wout,
                                           const float* __restrict__ bout,
                                           float* __restrict__ out){
    __shared__ float As[64][17];
    __shared__ float Ws[16][64];
    const int row0 = blockIdx.x*64;
    const int col0 = blockIdx.y*64;
    const int tid = threadIdx.x;
    const int tx = tid & 15;
    const int ty = tid >> 4;

    float acc[4][4];
#pragma unroll
    for (int i=0;i<4;i++)
#pragma unroll
        for (int j=0;j<4;j++) acc[i][j]=0.f;

    for (int k0=0;k0<768;k0+=16){
        {
            int r = tid >> 2;
            int kq = (tid & 3) << 2;
            int k = k0 + kq;
            float4 av;
            if (k < 512) av = *(const float4*)(d_Hbuf + (size_t)(row0+r)*Hn + k);
            else         av = *(const float4*)(d_Rbuf + (size_t)(row0+r)*(RR*CELLn) + (k-512));
            As[r][kq+0]=av.x; As[r][kq+1]=av.y; As[r][kq+2]=av.z; As[r][kq+3]=av.w;
        }
        {
            int kk = tid >> 4;
            int c4 = (tid & 15) << 2;
            *(float4*)&Ws[kk][c4] = *(const float4*)(Wout + (size_t)(k0+kk)*Hn + col0 + c4);
        }
        __syncthreads();
#pragma unroll
        for (int kk=0;kk<16;kk++){
            float4 w = *(const float4*)&Ws[kk][tx<<2];
            float a0 = As[(ty<<2)+0][kk];
            float a1 = As[(ty<<2)+1][kk];
            float a2 = As[(ty<<2)+2][kk];
            float a3 = As[(ty<<2)+3][kk];
            acc[0][0]+=a0*w.x; acc[0][1]+=a0*w.y; acc[0][2]+=a0*w.z; acc[0][3]+=a0*w.w;
            acc[1][0]+=a1*w.x; acc[1][1]+=a1*w.y; acc[1][2]+=a1*w.z; acc[1][3]+=a1*w.w;
            acc[2][0]+=a2*w.x; acc[2][1]+=a2*w.y; acc[2][2]+=a2*w.z; acc[2][3]+=a2*w.w;
            acc[3][0]+=a3*w.x; acc[3][1]+=a3*w.y; acc[3][2]+=a3*w.z; acc[3][3]+=a3*w.w;
        }
        __syncthreads();
    }
    float4 bb = *(const float4*)(bout + col0 + (tx<<2));
#pragma unroll
    for (int i=0;i<4;i++){
        int row = row0 + (ty<<2) + i;
        float4 v;
        v.x = fminf(fmaxf(acc[i][0]+bb.x,-CLIPf),CLIPf);
        v.y = fminf(fmaxf(acc[i][1]+bb.y,-CLIPf),CLIPf);
        v.z = fminf(fmaxf(acc[i][2]+bb.z,-CLIPf),CLIPf);
        v.w = fminf(fmaxf(acc[i][3]+bb.w,-CLIPf),CLIPf);
        *(float4*)(out + (size_t)row*Hn + col0 + (tx<<2)) = v;
    }
}

// ---------------- launch ----------------
extern "C" void kernel_launch(void* const* d_in, const int* in_sizes, int n_in,
                              void* d_out, int out_size){
    (void)in_sizes; (void)n_in; (void)out_size;
    const int*   source = (const int*)  d_in[0];
    const float* emb    = (const float*)d_in[2];
    const float* Wih    = (const float*)d_in[3];
    const float* Whh    = (const float*)d_in[4];
    const float* b_lstm = (const float*)d_in[5];
    const float* W_xi   = (const float*)d_in[6];
    const float* b_xi   = (const float*)d_in[7];
    const float* W_out  = (const float*)d_in[8];
    const float* b_out  = (const float*)d_in[9];
    float* out = (float*)d_out;

    k_init<<<128,256>>>();
    k_prep<<<1024,256>>>(W_xi);
    k_dummy<<<1,1>>>();     // exactly one: k_mega = process launch #6 for ncu -s 5 -c 1
    k_mega<<<NBLK,NTHR>>>(source, emb, Wih, Whh, b_lstm, b_xi);
    k_y<<<dim3(128,8),256>>>(W_out, b_out, out);
}